// round 14
// baseline (speedup 1.0000x reference)
#include <cuda_runtime.h>
#include <cuda_fp16.h>
#include <cstdint>

#define B_SZ  16
#define N_IN  6250
#define N_OUT 25000
#define CCH   64
#define SNB   9
#define NNZ   75000

// fp16 pooled [B][N_OUT][64] = 51.2 MB
__device__ unsigned short g_pooled_h[(size_t)B_SZ * N_OUT * CCH];
// W in mma-fragment order: [s][kk][nb][lane] -> (b0,b1), 72 KB
__device__ uint2 g_wfrag[SNB * 4 * 8 * 32];
// CSR scratch
__device__ int   g_cnt[N_OUT];
__device__ int   g_off[N_OUT + 1];
__device__ int   g_cur[N_OUT];
__device__ int   g_ecol[NNZ];
__device__ float g_eval[NNZ];

// ---------------------------------------------------------------------------
// helpers
// ---------------------------------------------------------------------------
__device__ __forceinline__ uint32_t smem_u32(const void* p) {
    uint32_t a;
    asm("{ .reg .u64 t; cvta.to.shared.u64 t, %1; cvt.u32.u64 %0, t; }"
        : "=r"(a) : "l"(p));
    return a;
}
__device__ __forceinline__ void cp16(uint32_t dst, const void* src) {
    asm volatile("cp.async.cg.shared.global [%0], [%1], 16;"
                 :: "r"(dst), "l"(src) : "memory");
}
__device__ __forceinline__ void cp_commit() {
    asm volatile("cp.async.commit_group;" ::: "memory");
}
template <int N>
__device__ __forceinline__ void cp_wait() {
    asm volatile("cp.async.wait_group %0;" :: "n"(N) : "memory");
}
__device__ __forceinline__ void ldm4(uint32_t* r, uint32_t addr) {
    asm volatile("ldmatrix.sync.aligned.m8n8.x4.shared.b16 {%0,%1,%2,%3}, [%4];"
                 : "=r"(r[0]), "=r"(r[1]), "=r"(r[2]), "=r"(r[3])
                 : "r"(addr));
}
__device__ __forceinline__ void mma16816(float* d, const uint32_t* a,
                                         const uint32_t* b) {
    asm volatile(
        "mma.sync.aligned.m16n8k16.row.col.f32.f16.f16.f32 "
        "{%0,%1,%2,%3},{%4,%5,%6,%7},{%8,%9},{%0,%1,%2,%3};"
        : "+f"(d[0]), "+f"(d[1]), "+f"(d[2]), "+f"(d[3])
        : "r"(a[0]), "r"(a[1]), "r"(a[2]), "r"(a[3]), "r"(b[0]), "r"(b[1]));
}

// ---------------------------------------------------------------------------
// prep: W fragment build (blocks 0..35) + csr_hist (blocks 36..328)
// g_cnt is zeroed by cudaMemsetAsync before this launch.
// ---------------------------------------------------------------------------
#define WFRAG_BLOCKS 36
#define HIST_BLOCKS  ((NNZ + 255) / 256)
__global__ void prep_kernel(const float* __restrict__ W,
                            const int* __restrict__ tr) {
    if (blockIdx.x < WFRAG_BLOCKS) {
        int i = blockIdx.x * 256 + threadIdx.x;
        if (i >= SNB * 4 * 8 * 32) return;
        int l  = i & 31;
        int nb = (i >> 5) & 7;
        int kk = (i >> 8) & 3;
        int s  = i >> 10;
        int n  = nb * 8 + (l >> 2);
        int k0 = s * 64 + kk * 16 + (l & 3) * 2;
        __half2 b0 = __halves2half2(
            __float2half_rn(__ldg(W + (size_t)k0 * 64 + n)),
            __float2half_rn(__ldg(W + (size_t)(k0 + 1) * 64 + n)));
        __half2 b1 = __halves2half2(
            __float2half_rn(__ldg(W + (size_t)(k0 + 8) * 64 + n)),
            __float2half_rn(__ldg(W + (size_t)(k0 + 9) * 64 + n)));
        uint2 v;
        v.x = *reinterpret_cast<uint32_t*>(&b0);
        v.y = *reinterpret_cast<uint32_t*>(&b1);
        g_wfrag[i] = v;
        return;
    }
    int t = (blockIdx.x - WFRAG_BLOCKS) * 256 + threadIdx.x;
    if (t < NNZ) atomicAdd(&g_cnt[__ldg(tr + t)], 1);
}

// ---------------------------------------------------------------------------
// CSR scan: two-level warp-shuffle scan
// ---------------------------------------------------------------------------
#define SCAN_T 1024
#define ROWS_PER_T 25
__global__ void __launch_bounds__(SCAN_T) csr_scan() {
    __shared__ int wsum[32];
    const int t    = threadIdx.x;
    const int lane = t & 31;
    const int wrp  = t >> 5;
    const int base = t * ROWS_PER_T;
    int local[ROWS_PER_T];
    int sum = 0;
#pragma unroll
    for (int i = 0; i < ROWS_PER_T; i++) {
        int r = base + i;
        local[i] = (r < N_OUT) ? g_cnt[r] : 0;
        sum += local[i];
    }
    int v = sum;
#pragma unroll
    for (int o = 1; o < 32; o <<= 1) {
        int u = __shfl_up_sync(0xFFFFFFFFu, v, o);
        if (lane >= o) v += u;
    }
    if (lane == 31) wsum[wrp] = v;
    __syncthreads();
    if (wrp == 0) {
        int w = wsum[lane];
#pragma unroll
        for (int o = 1; o < 32; o <<= 1) {
            int u = __shfl_up_sync(0xFFFFFFFFu, w, o);
            if (lane >= o) w += u;
        }
        wsum[lane] = w;
    }
    __syncthreads();
    int run = (wrp > 0 ? wsum[wrp - 1] : 0) + (v - sum);
#pragma unroll
    for (int i = 0; i < ROWS_PER_T; i++) {
        int r = base + i;
        if (r < N_OUT) {
            g_off[r] = run;
            g_cur[r] = run;
            run += local[i];
        }
    }
    if (t == SCAN_T - 1) g_off[N_OUT] = NNZ;
}

__global__ void csr_scatter(const float* __restrict__ tv,
                            const int* __restrict__ tr,
                            const int* __restrict__ tc) {
    int t = blockIdx.x * blockDim.x + threadIdx.x;
    if (t >= NNZ) return;
    int row = __ldg(tr + t);
    int pos = atomicAdd(&g_cur[row], 1);
    g_ecol[pos] = __ldg(tc + t);
    g_eval[pos] = __ldg(tv + t);
}

// ---------------------------------------------------------------------------
// pool_gather: covers 8 batches [bbase, bbase+8). 32 threads per output row,
// thread = cg (0..15) x b-half (0..1, 4 batches each). Simple entry loop
// (R12 body — unroll-2 regressed). fp32 acc -> fp16 store.
// ---------------------------------------------------------------------------
__global__ void __launch_bounds__(256) pool_gather(const float* __restrict__ x,
                                                   int bbase) {
    int t = blockIdx.x * blockDim.x + threadIdx.x;
    if (t >= N_OUT * 32) return;
    const int row = t >> 5;
    const int r   = t & 31;
    const int cg  = r & 15;
    const int b0  = bbase + (r >> 4) * 4;

    const int start = g_off[row];
    const int end   = g_off[row + 1];

    float4 acc[4];
#pragma unroll
    for (int b = 0; b < 4; b++) acc[b] = make_float4(0.f, 0.f, 0.f, 0.f);

    const float4* xp = reinterpret_cast<const float4*>(x);
    for (int i = start; i < end; i++) {
        int col = __ldg(g_ecol + i);
        float v = __ldg(g_eval + i);
        const float4* src = xp + ((size_t)b0 * N_IN + col) * 16 + cg;
#pragma unroll
        for (int b = 0; b < 4; b++) {
            float4 xv = src[(size_t)b * N_IN * 16];
            acc[b].x += v * xv.x;
            acc[b].y += v * xv.y;
            acc[b].z += v * xv.z;
            acc[b].w += v * xv.w;
        }
    }
#pragma unroll
    for (int b = 0; b < 4; b++) {
        ushort4 h;
        h.x = __half_as_ushort(__float2half_rn(acc[b].x));
        h.y = __half_as_ushort(__float2half_rn(acc[b].y));
        h.z = __half_as_ushort(__float2half_rn(acc[b].z));
        h.w = __half_as_ushort(__float2half_rn(acc[b].w));
        *reinterpret_cast<ushort4*>(
            g_pooled_h + ((size_t)(b0 + b) * N_OUT + row) * CCH + cg * 4) = h;
    }
}

// ---------------------------------------------------------------------------
// fused spiral gather + fp16 GEMM + bias + ELU  (R12-best mainloop, + bbase)
// CTA: 128 rows x 64 cols; 256 threads = 8 warps (4x2), warp tile 32x32.
// A-only ring 4 x 16 KB; staging lead 3; B fragments double-buffered.
// ---------------------------------------------------------------------------
#define STAGE_SZ  16384
#define NSTAGE    4
#define GEMM_SMEM (NSTAGE * STAGE_SZ)

__global__ void __launch_bounds__(256, 3) spiral_gemm_mma(
    const int*   __restrict__ sp,
    const float* __restrict__ bias,
    float*       __restrict__ out,
    int bbase) {
    extern __shared__ char smem[];
    const uint32_t sbase = smem_u32(smem);

    const int tid = threadIdx.x;
    const int l   = tid & 31;
    const int wid = tid >> 5;
    const int wm  = wid >> 1;
    const int wn  = wid & 1;
    const int b   = bbase + blockIdx.y;
    const int n0  = blockIdx.x * 128;

    const int arow  = tid >> 1;
    const int ahalf = tid & 1;
    const int rx    = arow & 7;

    const unsigned short* basePH = g_pooled_h + (size_t)b * N_OUT * CCH;
    const uint2* wfW = g_wfrag + (wn * 4) * 32 + l;

    float acc[2][4][4];
#pragma unroll
    for (int mi = 0; mi < 2; mi++)
#pragma unroll
        for (int nj = 0; nj < 4; nj++)
#pragma unroll
            for (int j = 0; j < 4; j++) acc[mi][nj][j] = 0.f;

    int nn = n0 + arow;
    if (nn >= N_OUT) nn = N_OUT - 1;
    const int* sprow = sp + (size_t)nn * SNB;

    auto stage = [&](int s) {
        const uint32_t stg = sbase + (s % NSTAGE) * STAGE_SZ;
        const int idx = __ldg(sprow + s);
        const char* srcA =
            (const char*)(basePH + (size_t)idx * CCH) + ahalf * 64;
        uint32_t dstA = stg + arow * 128;
#pragma unroll
        for (int j = 0; j < 4; j++) {
            int c = ahalf * 4 + j;
            cp16(dstA + ((c ^ rx) << 4), srcA + j * 16);
        }
        cp_commit();
    };

    auto compute = [&](int s) {
        const uint32_t stg = sbase + (s % NSTAGE) * STAGE_SZ;
        const uint2* wfS = wfW + (size_t)(s * 4) * 8 * 32;
        uint2 bv[2][4];
#pragma unroll
        for (int nj = 0; nj < 4; nj++) bv[0][nj] = __ldg(wfS + nj * 32);
#pragma unroll
        for (int kk = 0; kk < 4; kk++) {
            uint32_t ah[2][4];
#pragma unroll
            for (int mi = 0; mi < 2; mi++) {
                int row = wm * 32 + mi * 16 + (l & 15);
                int c = kk * 2 + (l >> 4);
                ldm4(ah[mi], stg + row * 128 + ((c ^ (row & 7)) << 4));
            }
            if (kk < 3) {
                const uint2* wfN = wfS + (size_t)(kk + 1) * 8 * 32;
#pragma unroll
                for (int nj = 0; nj < 4; nj++)
                    bv[(kk + 1) & 1][nj] = __ldg(wfN + nj * 32);
            }
#pragma unroll
            for (int mi = 0; mi < 2; mi++)
#pragma unroll
                for (int nj = 0; nj < 4; nj++)
                    mma16816(acc[mi][nj], ah[mi], &bv[kk & 1][nj].x);
        }
    };

    stage(0);
    stage(1);
    stage(2);
#pragma unroll
    for (int s = 0; s < SNB; s++) {
        cp_wait<2>();
        __syncthreads();
        if (s + 3 < SNB) stage(s + 3);
        else cp_commit();
        compute(s);
    }

    float bias8[4][2];
#pragma unroll
    for (int nj = 0; nj < 4; nj++) {
        int col = wn * 32 + nj * 8 + (l & 3) * 2;
        bias8[nj][0] = __ldg(bias + col);
        bias8[nj][1] = __ldg(bias + col + 1);
    }
#pragma unroll
    for (int mi = 0; mi < 2; mi++) {
#pragma unroll
        for (int half = 0; half < 2; half++) {
            int m = wm * 32 + mi * 16 + (l >> 2) + half * 8;
            int n = n0 + m;
            if (n >= N_OUT) continue;
            float* dst = out + ((size_t)b * N_OUT + n) * CCH;
#pragma unroll
            for (int nj = 0; nj < 4; nj++) {
                int col = wn * 32 + nj * 8 + (l & 3) * 2;
                float t0 = acc[mi][nj][half * 2 + 0] + bias8[nj][0];
                float t1 = acc[mi][nj][half * 2 + 1] + bias8[nj][1];
                float2 o;
                o.x = (t0 > 0.f) ? t0 : (__expf(t0) - 1.f);
                o.y = (t1 > 0.f) ? t1 : (__expf(t1) - 1.f);
                *reinterpret_cast<float2*>(dst + col) = o;
            }
        }
    }
}

// ---------------------------------------------------------------------------
// Fork-join overlap: pool[b8..15] on side stream concurrent with
// pool[b0..7] + gemm[b0..7] on the main (captured) stream.
// ---------------------------------------------------------------------------
extern "C" void kernel_launch(void* const* d_in, const int* in_sizes, int n_in,
                              void* d_out, int out_size) {
    const float* x    = (const float*)d_in[0];
    const float* tv   = (const float*)d_in[1];
    const int*   tr   = (const int*)d_in[2];
    const int*   tc   = (const int*)d_in[3];
    const int*   sp   = (const int*)d_in[4];
    const float* W    = (const float*)d_in[5];
    const float* bias = (const float*)d_in[6];
    float* out = (float*)d_out;

    static void* cnt_ptr = nullptr;
    static cudaStream_t sB = nullptr;
    static cudaEvent_t evScat = nullptr, evP1 = nullptr;
    static bool init_done = false;
    if (!init_done) {
        cudaFuncSetAttribute(spiral_gemm_mma,
                             cudaFuncAttributeMaxDynamicSharedMemorySize,
                             GEMM_SMEM);
        cudaGetSymbolAddress(&cnt_ptr, g_cnt);
        cudaStreamCreateWithFlags(&sB, cudaStreamNonBlocking);
        cudaEventCreateWithFlags(&evScat, cudaEventDisableTiming);
        cudaEventCreateWithFlags(&evP1, cudaEventDisableTiming);
        init_done = true;
    }

    const int poolGrid = (N_OUT * 32 + 255) / 256;
    dim3 gemmGrid((N_OUT + 127) / 128, 8);

    // main stream: CSR build
    cudaMemsetAsync(cnt_ptr, 0, N_OUT * sizeof(int), 0);
    prep_kernel<<<WFRAG_BLOCKS + HIST_BLOCKS, 256>>>(W, tr);
    csr_scan<<<1, SCAN_T>>>();
    csr_scatter<<<(NNZ + 255) / 256, 256>>>(tv, tr, tc);
    cudaEventRecord(evScat, 0);

    // side stream: pool for batches 8..15, concurrent with main chain
    cudaStreamWaitEvent(sB, evScat, 0);
    pool_gather<<<poolGrid, 256, 0, sB>>>(x, 8);
    cudaEventRecord(evP1, sB);

    // main stream: pool + gemm for batches 0..7, then gemm for 8..15
    pool_gather<<<poolGrid, 256>>>(x, 0);
    spiral_gemm_mma<<<gemmGrid, 256, GEMM_SMEM>>>(sp, bias, out, 0);
    cudaStreamWaitEvent(0, evP1, 0);
    spiral_gemm_mma<<<gemmGrid, 256, GEMM_SMEM>>>(sp, bias, out, 8);
}

// round 15
// speedup vs baseline: 1.0570x; 1.0570x over previous
#include <cuda_runtime.h>
#include <cuda_fp16.h>
#include <cstdint>

#define B_SZ  16
#define N_IN  6250
#define N_OUT 25000
#define CCH   64
#define SNB   9
#define NNZ   75000

// fp16 pooled [B][N_OUT][64] = 51.2 MB
__device__ unsigned short g_pooled_h[(size_t)B_SZ * N_OUT * CCH];
// W in mma-fragment order: [s][kk][nb][lane] -> (b0,b1), 72 KB
__device__ uint2 g_wfrag[SNB * 4 * 8 * 32];
// CSR scratch
__device__ int   g_cnt[N_OUT];
__device__ int   g_off[N_OUT + 1];
__device__ int   g_cur[N_OUT];
__device__ int   g_ecol[NNZ];
__device__ float g_eval[NNZ];

// ---------------------------------------------------------------------------
// helpers
// ---------------------------------------------------------------------------
__device__ __forceinline__ uint32_t smem_u32(const void* p) {
    uint32_t a;
    asm("{ .reg .u64 t; cvta.to.shared.u64 t, %1; cvt.u32.u64 %0, t; }"
        : "=r"(a) : "l"(p));
    return a;
}
__device__ __forceinline__ void cp16(uint32_t dst, const void* src) {
    asm volatile("cp.async.cg.shared.global [%0], [%1], 16;"
                 :: "r"(dst), "l"(src) : "memory");
}
__device__ __forceinline__ void cp_commit() {
    asm volatile("cp.async.commit_group;" ::: "memory");
}
template <int N>
__device__ __forceinline__ void cp_wait() {
    asm volatile("cp.async.wait_group %0;" :: "n"(N) : "memory");
}
__device__ __forceinline__ void ldm4(uint32_t* r, uint32_t addr) {
    asm volatile("ldmatrix.sync.aligned.m8n8.x4.shared.b16 {%0,%1,%2,%3}, [%4];"
                 : "=r"(r[0]), "=r"(r[1]), "=r"(r[2]), "=r"(r[3])
                 : "r"(addr));
}
__device__ __forceinline__ void mma16816(float* d, const uint32_t* a,
                                         const uint32_t* b) {
    asm volatile(
        "mma.sync.aligned.m16n8k16.row.col.f32.f16.f16.f32 "
        "{%0,%1,%2,%3},{%4,%5,%6,%7},{%8,%9},{%0,%1,%2,%3};"
        : "+f"(d[0]), "+f"(d[1]), "+f"(d[2]), "+f"(d[3])
        : "r"(a[0]), "r"(a[1]), "r"(a[2]), "r"(a[3]), "r"(b[0]), "r"(b[1]));
}
__device__ __forceinline__ void stcs2(float* p, float a, float b) {
    float2 v = make_float2(a, b);
    asm volatile("st.global.cs.v2.f32 [%0], {%1, %2};"
                 :: "l"(p), "f"(v.x), "f"(v.y) : "memory");
}

// ---------------------------------------------------------------------------
// prep: W fragment build (blocks 0..35) + csr_hist (blocks 36..328)
// g_cnt is zeroed by cudaMemsetAsync before this launch.
// ---------------------------------------------------------------------------
#define WFRAG_BLOCKS 36
#define HIST_BLOCKS  ((NNZ + 255) / 256)
__global__ void prep_kernel(const float* __restrict__ W,
                            const int* __restrict__ tr) {
    if (blockIdx.x < WFRAG_BLOCKS) {
        int i = blockIdx.x * 256 + threadIdx.x;
        if (i >= SNB * 4 * 8 * 32) return;
        int l  = i & 31;
        int nb = (i >> 5) & 7;
        int kk = (i >> 8) & 3;
        int s  = i >> 10;
        int n  = nb * 8 + (l >> 2);
        int k0 = s * 64 + kk * 16 + (l & 3) * 2;
        __half2 b0 = __halves2half2(
            __float2half_rn(__ldg(W + (size_t)k0 * 64 + n)),
            __float2half_rn(__ldg(W + (size_t)(k0 + 1) * 64 + n)));
        __half2 b1 = __halves2half2(
            __float2half_rn(__ldg(W + (size_t)(k0 + 8) * 64 + n)),
            __float2half_rn(__ldg(W + (size_t)(k0 + 9) * 64 + n)));
        uint2 v;
        v.x = *reinterpret_cast<uint32_t*>(&b0);
        v.y = *reinterpret_cast<uint32_t*>(&b1);
        g_wfrag[i] = v;
        return;
    }
    int t = (blockIdx.x - WFRAG_BLOCKS) * 256 + threadIdx.x;
    if (t < NNZ) atomicAdd(&g_cnt[__ldg(tr + t)], 1);
}

// ---------------------------------------------------------------------------
// CSR scan: two-level warp-shuffle scan
// ---------------------------------------------------------------------------
#define SCAN_T 1024
#define ROWS_PER_T 25
__global__ void __launch_bounds__(SCAN_T) csr_scan() {
    __shared__ int wsum[32];
    const int t    = threadIdx.x;
    const int lane = t & 31;
    const int wrp  = t >> 5;
    const int base = t * ROWS_PER_T;
    int local[ROWS_PER_T];
    int sum = 0;
#pragma unroll
    for (int i = 0; i < ROWS_PER_T; i++) {
        int r = base + i;
        local[i] = (r < N_OUT) ? g_cnt[r] : 0;
        sum += local[i];
    }
    int v = sum;
#pragma unroll
    for (int o = 1; o < 32; o <<= 1) {
        int u = __shfl_up_sync(0xFFFFFFFFu, v, o);
        if (lane >= o) v += u;
    }
    if (lane == 31) wsum[wrp] = v;
    __syncthreads();
    if (wrp == 0) {
        int w = wsum[lane];
#pragma unroll
        for (int o = 1; o < 32; o <<= 1) {
            int u = __shfl_up_sync(0xFFFFFFFFu, w, o);
            if (lane >= o) w += u;
        }
        wsum[lane] = w;
    }
    __syncthreads();
    int run = (wrp > 0 ? wsum[wrp - 1] : 0) + (v - sum);
#pragma unroll
    for (int i = 0; i < ROWS_PER_T; i++) {
        int r = base + i;
        if (r < N_OUT) {
            g_off[r] = run;
            g_cur[r] = run;
            run += local[i];
        }
    }
    if (t == SCAN_T - 1) g_off[N_OUT] = NNZ;
}

__global__ void csr_scatter(const float* __restrict__ tv,
                            const int* __restrict__ tr,
                            const int* __restrict__ tc) {
    int t = blockIdx.x * blockDim.x + threadIdx.x;
    if (t >= NNZ) return;
    int row = __ldg(tr + t);
    int pos = atomicAdd(&g_cur[row], 1);
    g_ecol[pos] = __ldg(tc + t);
    g_eval[pos] = __ldg(tv + t);
}

// ---------------------------------------------------------------------------
// pool_gather: 64 threads (2 warps) per output row, all 16 batches.
// thread = cg (0..15) x b-quarter (0..3, 4 batches each).
// Simple entry loop (proven best). fp32 acc -> fp16 store.
// ---------------------------------------------------------------------------
__global__ void __launch_bounds__(256) pool_gather(const float* __restrict__ x) {
    int t = blockIdx.x * blockDim.x + threadIdx.x;
    if (t >= N_OUT * 64) return;
    const int row = t >> 6;
    const int r   = t & 63;
    const int cg  = r & 15;
    const int b0  = (r >> 4) * 4;

    const int start = g_off[row];
    const int end   = g_off[row + 1];

    float4 acc[4];
#pragma unroll
    for (int b = 0; b < 4; b++) acc[b] = make_float4(0.f, 0.f, 0.f, 0.f);

    const float4* xp = reinterpret_cast<const float4*>(x);
    for (int i = start; i < end; i++) {
        int col = __ldg(g_ecol + i);
        float v = __ldg(g_eval + i);
        const float4* src = xp + ((size_t)b0 * N_IN + col) * 16 + cg;
#pragma unroll
        for (int b = 0; b < 4; b++) {
            float4 xv = src[(size_t)b * N_IN * 16];
            acc[b].x += v * xv.x;
            acc[b].y += v * xv.y;
            acc[b].z += v * xv.z;
            acc[b].w += v * xv.w;
        }
    }
#pragma unroll
    for (int b = 0; b < 4; b++) {
        ushort4 h;
        h.x = __half_as_ushort(__float2half_rn(acc[b].x));
        h.y = __half_as_ushort(__float2half_rn(acc[b].y));
        h.z = __half_as_ushort(__float2half_rn(acc[b].z));
        h.w = __half_as_ushort(__float2half_rn(acc[b].w));
        *reinterpret_cast<ushort4*>(
            g_pooled_h + ((size_t)(b0 + b) * N_OUT + row) * CCH + cg * 4) = h;
    }
}

// ---------------------------------------------------------------------------
// fused spiral gather + fp16 GEMM + bias + ELU  (182.08 µs mainloop, exact)
// CTA: 128 rows x 64 cols; 256 threads = 8 warps (4x2), warp tile 32x32.
// A-only ring 4 x 16 KB; staging lead 3; B fragments double-buffered.
// Output via streaming stores (st.global.cs) to preserve L2 for gathers.
// ---------------------------------------------------------------------------
#define STAGE_SZ  16384
#define NSTAGE    4
#define GEMM_SMEM (NSTAGE * STAGE_SZ)

__global__ void __launch_bounds__(256, 3) spiral_gemm_mma(
    const int*   __restrict__ sp,
    const float* __restrict__ bias,
    float*       __restrict__ out) {
    extern __shared__ char smem[];
    const uint32_t sbase = smem_u32(smem);

    const int tid = threadIdx.x;
    const int l   = tid & 31;
    const int wid = tid >> 5;
    const int wm  = wid >> 1;
    const int wn  = wid & 1;
    const int b   = blockIdx.y;
    const int n0  = blockIdx.x * 128;

    const int arow  = tid >> 1;
    const int ahalf = tid & 1;
    const int rx    = arow & 7;

    const unsigned short* basePH = g_pooled_h + (size_t)b * N_OUT * CCH;
    const uint2* wfW = g_wfrag + (wn * 4) * 32 + l;

    float acc[2][4][4];
#pragma unroll
    for (int mi = 0; mi < 2; mi++)
#pragma unroll
        for (int nj = 0; nj < 4; nj++)
#pragma unroll
            for (int j = 0; j < 4; j++) acc[mi][nj][j] = 0.f;

    int nn = n0 + arow;
    if (nn >= N_OUT) nn = N_OUT - 1;
    const int* sprow = sp + (size_t)nn * SNB;

    auto stage = [&](int s) {
        const uint32_t stg = sbase + (s % NSTAGE) * STAGE_SZ;
        const int idx = __ldg(sprow + s);
        const char* srcA =
            (const char*)(basePH + (size_t)idx * CCH) + ahalf * 64;
        uint32_t dstA = stg + arow * 128;
#pragma unroll
        for (int j = 0; j < 4; j++) {
            int c = ahalf * 4 + j;
            cp16(dstA + ((c ^ rx) << 4), srcA + j * 16);
        }
        cp_commit();
    };

    auto compute = [&](int s) {
        const uint32_t stg = sbase + (s % NSTAGE) * STAGE_SZ;
        const uint2* wfS = wfW + (size_t)(s * 4) * 8 * 32;
        uint2 bv[2][4];
#pragma unroll
        for (int nj = 0; nj < 4; nj++) bv[0][nj] = __ldg(wfS + nj * 32);
#pragma unroll
        for (int kk = 0; kk < 4; kk++) {
            uint32_t ah[2][4];
#pragma unroll
            for (int mi = 0; mi < 2; mi++) {
                int row = wm * 32 + mi * 16 + (l & 15);
                int c = kk * 2 + (l >> 4);
                ldm4(ah[mi], stg + row * 128 + ((c ^ (row & 7)) << 4));
            }
            if (kk < 3) {
                const uint2* wfN = wfS + (size_t)(kk + 1) * 8 * 32;
#pragma unroll
                for (int nj = 0; nj < 4; nj++)
                    bv[(kk + 1) & 1][nj] = __ldg(wfN + nj * 32);
            }
#pragma unroll
            for (int mi = 0; mi < 2; mi++)
#pragma unroll
                for (int nj = 0; nj < 4; nj++)
                    mma16816(acc[mi][nj], ah[mi], &bv[kk & 1][nj].x);
        }
    };

    stage(0);
    stage(1);
    stage(2);
#pragma unroll
    for (int s = 0; s < SNB; s++) {
        cp_wait<2>();
        __syncthreads();
        if (s + 3 < SNB) stage(s + 3);
        else cp_commit();
        compute(s);
    }

    float bias8[4][2];
#pragma unroll
    for (int nj = 0; nj < 4; nj++) {
        int col = wn * 32 + nj * 8 + (l & 3) * 2;
        bias8[nj][0] = __ldg(bias + col);
        bias8[nj][1] = __ldg(bias + col + 1);
    }
#pragma unroll
    for (int mi = 0; mi < 2; mi++) {
#pragma unroll
        for (int half = 0; half < 2; half++) {
            int m = wm * 32 + mi * 16 + (l >> 2) + half * 8;
            int n = n0 + m;
            if (n >= N_OUT) continue;
            float* dst = out + ((size_t)b * N_OUT + n) * CCH;
#pragma unroll
            for (int nj = 0; nj < 4; nj++) {
                int col = wn * 32 + nj * 8 + (l & 3) * 2;
                float t0 = acc[mi][nj][half * 2 + 0] + bias8[nj][0];
                float t1 = acc[mi][nj][half * 2 + 1] + bias8[nj][1];
                float o0 = (t0 > 0.f) ? t0 : (__expf(t0) - 1.f);
                float o1 = (t1 > 0.f) ? t1 : (__expf(t1) - 1.f);
                stcs2(dst + col, o0, o1);   // streaming: evict-first
            }
        }
    }
}

// ---------------------------------------------------------------------------
extern "C" void kernel_launch(void* const* d_in, const int* in_sizes, int n_in,
                              void* d_out, int out_size) {
    const float* x    = (const float*)d_in[0];
    const float* tv   = (const float*)d_in[1];
    const int*   tr   = (const int*)d_in[2];
    const int*   tc   = (const int*)d_in[3];
    const int*   sp   = (const int*)d_in[4];
    const float* W    = (const float*)d_in[5];
    const float* bias = (const float*)d_in[6];
    float* out = (float*)d_out;

    static void* cnt_ptr = nullptr;
    static bool attr_set = false;
    if (!attr_set) {
        cudaFuncSetAttribute(spiral_gemm_mma,
                             cudaFuncAttributeMaxDynamicSharedMemorySize,
                             GEMM_SMEM);
        cudaGetSymbolAddress(&cnt_ptr, g_cnt);
        attr_set = true;
    }

    cudaMemsetAsync(cnt_ptr, 0, N_OUT * sizeof(int), 0);
    prep_kernel<<<WFRAG_BLOCKS + HIST_BLOCKS, 256>>>(W, tr);
    csr_scan<<<1, SCAN_T>>>();
    csr_scatter<<<(NNZ + 255) / 256, 256>>>(tv, tr, tc);
    pool_gather<<<(N_OUT * 64 + 255) / 256, 256>>>(x);

    dim3 grid((N_OUT + 127) / 128, B_SZ);
    spiral_gemm_mma<<<grid, 256, GEMM_SMEM>>>(sp, bias, out);
}